// round 11
// baseline (speedup 1.0000x reference)
#include <cuda_runtime.h>
#include <cstdint>

// YOLO detection postprocess:
//   in : (16, 25200, 85) f32   [xc, yc, w, h, conf, cls0..cls79]
//   out: (16, 25200, 6)  f32   [xmin, ymin, xmax, ymax, conf*maxcls, argmax] or zeros
//
// Warp-autonomous cp.async pipelines: each warp owns a 16-row tile stream with
// its own 2-stage double buffer (cp.async groups are per-thread state), synced
// only with __syncwarp -> no block barriers, 20 decorrelated streams/SM.

#define CONF_THRESH 0.25f
#define ROW_LEN 85
#define OUT_LEN 6
#define WROWS 16                                   // rows per warp-tile
#define WARPS 4
#define THREADS (WARPS * 32)
#define TILE_FLOATS (WROWS * ROW_LEN)              // 1360
#define TILE_VEC4   (TILE_FLOATS / 4)              // 340
#define VEC_FULL    (TILE_VEC4 / 32)               // 10
#define VEC_REM     (TILE_VEC4 - VEC_FULL * 32)    // 20

__device__ __forceinline__ void cp16(uint32_t dst_smem, const void* src_gmem) {
    asm volatile("cp.async.cg.shared.global [%0], [%1], 16;\n"
                 :: "r"(dst_smem), "l"(src_gmem));
}

__device__ __forceinline__ void prefetch_tile(uint32_t sb, const float* __restrict__ in,
                                              int tile, int lane)
{
    const float4* src = (const float4*)(in + (size_t)tile * TILE_FLOATS);
#pragma unroll
    for (int i = 0; i < VEC_FULL; i++)
        cp16(sb + (uint32_t)(lane + i * 32) * 16, src + lane + i * 32);
    if (lane < VEC_REM)
        cp16(sb + (uint32_t)(lane + VEC_FULL * 32) * 16, src + lane + VEC_FULL * 32);
}

__global__ __launch_bounds__(THREADS) void yolo_post_kernel(
    const float* __restrict__ in, float* __restrict__ out, int ntiles)
{
    __shared__ __align__(16) float buf[WARPS][2][TILE_FLOATS];

    const int lane = threadIdx.x & 31;
    const int wid  = threadIdx.x >> 5;
    const int step = gridDim.x * WARPS;            // total warp-streams

    uint32_t sbase[2];
    sbase[0] = (uint32_t)__cvta_generic_to_shared(buf[wid][0]);
    sbase[1] = (uint32_t)__cvta_generic_to_shared(buf[wid][1]);

    int tile = blockIdx.x * WARPS + wid;

    // Prologue: prefetch first tile into stage 0
    if (tile < ntiles)
        prefetch_tile(sbase[0], in, tile, lane);
    asm volatile("cp.async.commit_group;\n");

    const int r = lane >> 1;                       // row within tile (0..15)
    const int q = lane & 1;                        // half: classes [40q, 40q+40)

    int stage = 0;
    while (tile < ntiles) {
        // Prefetch next tile into the other stage
        const int next = tile + step;
        if (next < ntiles)
            prefetch_tile(sbase[stage ^ 1], in, next, lane);
        asm volatile("cp.async.commit_group;\n");

        // Wait for current tile's group (just-issued prefetch keeps flying)
        asm volatile("cp.async.wait_group 1;\n");
        __syncwarp();

        // ---- Compute: 2 lanes per row, two interleaved max-chains ----
        const float* rp = buf[wid][stage] + r * ROW_LEN;
        const float* cp = rp + 5 + 40 * q;

        float b0 = cp[0]; int i0 = 0;
        float b1 = cp[1]; int i1 = 1;
#pragma unroll
        for (int c = 2; c < 40; c += 2) {
            const float v0 = cp[c];
            const float v1 = cp[c + 1];
            if (v0 > b0) { b0 = v0; i0 = c; }      // strict > : first max
            if (v1 > b1) { b1 = v1; i1 = c + 1; }
        }
        // Merge chains; tie -> smaller index (jnp.argmax first-occurrence)
        float best; int bidx;
        if (b1 > b0 || (b1 == b0 && i1 < i0)) { best = b1; bidx = i1; }
        else                                   { best = b0; bidx = i0; }
        bidx += 40 * q;

        // Combine across the lane pair; tie -> lowest class index
        {
            const float ob = __shfl_xor_sync(0xffffffffu, best, 1);
            const int   oi = __shfl_xor_sync(0xffffffffu, bidx, 1);
            if (ob > best || (ob == best && oi < bidx)) { best = ob; bidx = oi; }
        }

        const float x = rp[0], y = rp[1], w = rp[2], h = rp[3], conf = rp[4];
        const float score = conf * best;
        const bool  keep  = score > CONF_THRESH;
        const float hw = 0.5f * w;
        const float hh = 0.5f * h;

        float2* orow = reinterpret_cast<float2*>(out + (size_t)(tile * WROWS + r) * OUT_LEN);
        if (q == 0) {
            orow[0] = keep ? make_float2(x - hw, y - hh) : make_float2(0.f, 0.f);
            orow[1] = keep ? make_float2(x + hw, y + hh) : make_float2(0.f, 0.f);
        } else {
            orow[2] = keep ? make_float2(score, (float)bidx) : make_float2(0.f, 0.f);
        }

        // All lanes done reading this stage before next prefetch overwrites it.
        __syncwarp();

        tile = next;
        stage ^= 1;
    }
}

extern "C" void kernel_launch(void* const* d_in, const int* in_sizes, int n_in,
                              void* d_out, int out_size)
{
    const float* in  = (const float*)d_in[0];
    float*       out = (float*)d_out;

    const int nrows  = in_sizes[0] / ROW_LEN;     // 403200
    const int ntiles = nrows / WROWS;             // 25200 (exact)

    // Persistent grid: 5 blocks/SM x 148 SMs -> 2960 warp-streams
    const int blocks = 740;

    yolo_post_kernel<<<blocks, THREADS>>>(in, out, ntiles);
}

// round 12
// speedup vs baseline: 1.0717x; 1.0717x over previous
#include <cuda_runtime.h>
#include <cstdint>

// YOLO detection postprocess:
//   in : (16, 25200, 85) f32   [xc, yc, w, h, conf, cls0..cls79]
//   out: (16, 25200, 6)  f32   [xmin, ymin, xmax, ymax, conf*maxcls, argmax] or zeros
//
// Persistent blocks, cp.async.cg 4-stage ring with depth-3 prefetch:
//   - 32 rows/stage (10880 B) x 4 stages = 43520 B static smem -> 5 blocks/SM
//   - 128 threads: 4 lanes/row, 20 classes each; 2 interleaved chains +
//     shfl_xor merges; one __syncthreads per tile.

#define CONF_THRESH 0.25f
#define ROW_LEN 85
#define OUT_LEN 6
#define WROWS 32                                    // rows per stage/tile
#define STAGES 4
#define THREADS 128
#define TILE_FLOATS (WROWS * ROW_LEN)               // 2720
#define TILE_VEC4   (TILE_FLOATS / 4)               // 680
#define VEC_FULL    (TILE_VEC4 / THREADS)           // 5
#define VEC_REM     (TILE_VEC4 - VEC_FULL * THREADS) // 40

__device__ __forceinline__ void cp16(uint32_t dst_smem, const void* src_gmem) {
    asm volatile("cp.async.cg.shared.global [%0], [%1], 16;\n"
                 :: "r"(dst_smem), "l"(src_gmem));
}

__device__ __forceinline__ void prefetch_tile(uint32_t sb, const float* __restrict__ in,
                                              int tile, int tid)
{
    const float4* src = (const float4*)(in + (size_t)tile * TILE_FLOATS);
#pragma unroll
    for (int i = 0; i < VEC_FULL; i++)
        cp16(sb + (uint32_t)(tid + i * THREADS) * 16, src + tid + i * THREADS);
    if (tid < VEC_REM)
        cp16(sb + (uint32_t)(tid + VEC_FULL * THREADS) * 16,
             src + tid + VEC_FULL * THREADS);
}

__global__ __launch_bounds__(THREADS) void yolo_post_kernel(
    const float* __restrict__ in, float* __restrict__ out, int ntiles)
{
    __shared__ __align__(16) float buf[STAGES][TILE_FLOATS];

    const int tid  = threadIdx.x;
    const int step = gridDim.x;

    uint32_t sbase[STAGES];
#pragma unroll
    for (int s = 0; s < STAGES; s++)
        sbase[s] = (uint32_t)__cvta_generic_to_shared(buf[s]);

    // Prologue: prefetch tiles j=0,1,2 into stages 0,1,2 (3 committed groups)
#pragma unroll
    for (int p = 0; p < 3; p++) {
        const int t = blockIdx.x + p * step;
        if (t < ntiles)
            prefetch_tile(sbase[p], in, t, tid);
        asm volatile("cp.async.commit_group;\n");
    }

    const int r = tid >> 2;                        // row within tile (0..31)
    const int q = tid & 3;                         // quarter: classes [20q,20q+20)

    int j = 0;
    int tile = blockIdx.x;
    while (tile < ntiles) {
        // Oldest of the <=3 outstanding groups is tile j's data
        asm volatile("cp.async.wait_group 2;\n");
        __syncthreads();   // also: everyone finished computing tile j-1 last iter

        // Prefetch tile j+3 into stage (j+3)%4 (= stage of tile j-1, now free)
        const int pf = tile + 3 * step;
        if (pf < ntiles)
            prefetch_tile(sbase[(j + 3) & 3], in, pf, tid);
        asm volatile("cp.async.commit_group;\n");

        // ---- Compute tile j: 4 lanes per row ----
        const float* rp = buf[j & 3] + r * ROW_LEN;
        const float* cp = rp + 5 + 20 * q;

        float b0 = cp[0]; int i0 = 0;
        float b1 = cp[1]; int i1 = 1;
#pragma unroll
        for (int c = 2; c < 20; c += 2) {
            const float v0 = cp[c];
            const float v1 = cp[c + 1];
            if (v0 > b0) { b0 = v0; i0 = c; }      // strict > : first max
            if (v1 > b1) { b1 = v1; i1 = c + 1; }
        }
        // Merge chains; tie -> smaller index (jnp.argmax first-occurrence)
        float best; int bidx;
        if (b1 > b0 || (b1 == b0 && i1 < i0)) { best = b1; bidx = i1; }
        else                                   { best = b0; bidx = i0; }
        bidx += 20 * q;

        // Combine across the 4-lane group; tie -> lowest class index
#pragma unroll
        for (int off = 1; off <= 2; off <<= 1) {
            const float ob = __shfl_xor_sync(0xffffffffu, best, off);
            const int   oi = __shfl_xor_sync(0xffffffffu, bidx, off);
            if (ob > best || (ob == best && oi < bidx)) { best = ob; bidx = oi; }
        }

        const float conf  = rp[4];
        const float score = conf * best;
        const bool  keep  = score > CONF_THRESH;

        float2* orow = reinterpret_cast<float2*>(out + (size_t)(tile * WROWS + r) * OUT_LEN);
        if (q == 0) {
            const float x = rp[0], y = rp[1], w = rp[2], h = rp[3];
            const float hw = 0.5f * w;
            const float hh = 0.5f * h;
            orow[0] = keep ? make_float2(x - hw, y - hh) : make_float2(0.f, 0.f);
            orow[1] = keep ? make_float2(x + hw, y + hh) : make_float2(0.f, 0.f);
        } else if (q == 1) {
            orow[2] = keep ? make_float2(score, (float)bidx) : make_float2(0.f, 0.f);
        }

        j++;
        tile += step;
    }
}

extern "C" void kernel_launch(void* const* d_in, const int* in_sizes, int n_in,
                              void* d_out, int out_size)
{
    const float* in  = (const float*)d_in[0];
    float*       out = (float*)d_out;

    const int nrows  = in_sizes[0] / ROW_LEN;     // 403200
    const int ntiles = nrows / WROWS;             // 12600 (exact)

    // Persistent grid: 5 blocks/SM x 148 SMs
    const int blocks = 740;

    yolo_post_kernel<<<blocks, THREADS>>>(in, out, ntiles);
}

// round 13
// speedup vs baseline: 1.0811x; 1.0088x over previous
#include <cuda_runtime.h>
#include <cstdint>

// YOLO detection postprocess:
//   in : (16, 25200, 85) f32   [xc, yc, w, h, conf, cls0..cls79]
//   out: (16, 25200, 6)  f32   [xmin, ymin, xmax, ymax, conf*maxcls, argmax] or zeros
//
// Persistent blocks; TMA bulk (cp.async.bulk + mbarrier) 4-stage ring, depth-3:
//   - 32 rows/stage = 10880 B contiguous GMEM -> ONE bulk copy per tile
//     (replaces ~680 LDGSTS; SM issue path left free for compute LDS)
//   - 128 threads: 4 lanes/row, 20 classes each; interleaved max-chains +
//     shfl_xor merges with first-index tie-break.

#define CONF_THRESH 0.25f
#define ROW_LEN 85
#define OUT_LEN 6
#define WROWS 32
#define STAGES 4
#define THREADS 128
#define TILE_FLOATS (WROWS * ROW_LEN)       // 2720
#define TILE_BYTES  (TILE_FLOATS * 4)       // 10880 (16B multiple)

__device__ __forceinline__ void mbar_init(uint32_t mbar, uint32_t count) {
    asm volatile("mbarrier.init.shared::cta.b64 [%0], %1;"
                 :: "r"(mbar), "r"(count) : "memory");
}

__device__ __forceinline__ void mbar_expect_tx(uint32_t mbar, uint32_t bytes) {
    asm volatile("mbarrier.arrive.expect_tx.shared::cta.b64 _, [%0], %1;"
                 :: "r"(mbar), "r"(bytes) : "memory");
}

__device__ __forceinline__ void bulk_ld(uint32_t dst, const void* src,
                                        uint32_t bytes, uint32_t mbar) {
    asm volatile(
        "cp.async.bulk.shared::cta.global.mbarrier::complete_tx::bytes "
        "[%0], [%1], %2, [%3];"
        :: "r"(dst), "l"(src), "r"(bytes), "r"(mbar) : "memory");
}

__device__ __forceinline__ void mbar_wait(uint32_t mbar, uint32_t parity) {
    asm volatile(
        "{\n\t"
        ".reg .pred P;\n\t"
        "WAIT_%=:\n\t"
        "mbarrier.try_wait.parity.acquire.cta.shared::cta.b64 P, [%0], %1, 0x989680;\n\t"
        "@!P bra WAIT_%=;\n\t"
        "}"
        :: "r"(mbar), "r"(parity) : "memory");
}

__global__ __launch_bounds__(THREADS) void yolo_post_kernel(
    const float* __restrict__ in, float* __restrict__ out, int ntiles)
{
    __shared__ __align__(16) float buf[STAGES][TILE_FLOATS];
    __shared__ __align__(8) unsigned long long mbar[STAGES];

    const int tid  = threadIdx.x;
    const int step = gridDim.x;

    const uint32_t mb0 = (uint32_t)__cvta_generic_to_shared(&mbar[0]);
    uint32_t sb[STAGES];
#pragma unroll
    for (int s = 0; s < STAGES; s++)
        sb[s] = (uint32_t)__cvta_generic_to_shared(buf[s]);

    if (tid == 0) {
#pragma unroll
        for (int s = 0; s < STAGES; s++)
            mbar_init(mb0 + s * 8, 1);
    }
    __syncthreads();

    // Prologue: issue tiles j=0,1,2 into stages 0,1,2
    if (tid == 0) {
#pragma unroll
        for (int p = 0; p < 3; p++) {
            const int t = blockIdx.x + p * step;
            if (t < ntiles) {
                mbar_expect_tx(mb0 + p * 8, TILE_BYTES);
                bulk_ld(sb[p], in + (size_t)t * TILE_FLOATS, TILE_BYTES, mb0 + p * 8);
            }
        }
    }

    const int r = tid >> 2;                 // row within tile (0..31)
    const int q = tid & 3;                  // quarter: classes [20q, 20q+20)

    int j = 0;
    int tile = blockIdx.x;
    while (tile < ntiles) {
        const int s = j & 3;

        // Issue tile j+3 into stage (j+3)&3 (tile j-1's stage; its compute
        // finished before last iteration's __syncthreads).
        if (tid == 0) {
            const int pf = tile + 3 * step;
            if (pf < ntiles) {
                const int ps = (j + 3) & 3;
                mbar_expect_tx(mb0 + ps * 8, TILE_BYTES);
                bulk_ld(sb[ps], in + (size_t)pf * TILE_FLOATS, TILE_BYTES, mb0 + ps * 8);
            }
        }

        // Wait for tile j's data; stage s refilled once per lap -> parity = lap&1
        mbar_wait(mb0 + s * 8, (j >> 2) & 1);

        // ---- Compute tile j: 4 lanes per row ----
        const float* rp = buf[s] + r * ROW_LEN;
        const float* cp = rp + 5 + 20 * q;

        float b0 = cp[0]; int i0 = 0;
        float b1 = cp[1]; int i1 = 1;
#pragma unroll
        for (int c = 2; c < 20; c += 2) {
            const float v0 = cp[c];
            const float v1 = cp[c + 1];
            if (v0 > b0) { b0 = v0; i0 = c; }   // strict > : first max
            if (v1 > b1) { b1 = v1; i1 = c + 1; }
        }
        // Merge chains; tie -> smaller index (jnp.argmax first-occurrence)
        float best; int bidx;
        if (b1 > b0 || (b1 == b0 && i1 < i0)) { best = b1; bidx = i1; }
        else                                   { best = b0; bidx = i0; }
        bidx += 20 * q;

        // Combine across the 4-lane group; tie -> lowest class index
#pragma unroll
        for (int off = 1; off <= 2; off <<= 1) {
            const float ob = __shfl_xor_sync(0xffffffffu, best, off);
            const int   oi = __shfl_xor_sync(0xffffffffu, bidx, off);
            if (ob > best || (ob == best && oi < bidx)) { best = ob; bidx = oi; }
        }

        const float conf  = rp[4];
        const float score = conf * best;
        const bool  keep  = score > CONF_THRESH;

        float2* orow = reinterpret_cast<float2*>(out + (size_t)(tile * WROWS + r) * OUT_LEN);
        if (q == 0) {
            const float x = rp[0], y = rp[1], w = rp[2], h = rp[3];
            const float hw = 0.5f * w;
            const float hh = 0.5f * h;
            orow[0] = keep ? make_float2(x - hw, y - hh) : make_float2(0.f, 0.f);
            orow[1] = keep ? make_float2(x + hw, y + hh) : make_float2(0.f, 0.f);
        } else if (q == 1) {
            orow[2] = keep ? make_float2(score, (float)bidx) : make_float2(0.f, 0.f);
        }

        // All threads done reading stage s before it is re-issued next iter.
        __syncthreads();

        j++;
        tile += step;
    }
}

extern "C" void kernel_launch(void* const* d_in, const int* in_sizes, int n_in,
                              void* d_out, int out_size)
{
    const float* in  = (const float*)d_in[0];
    float*       out = (float*)d_out;

    const int nrows  = in_sizes[0] / ROW_LEN;    // 403200
    const int ntiles = nrows / WROWS;            // 12600 (exact)

    // Persistent grid: 5 blocks/SM x 148 SMs
    const int blocks = 740;

    yolo_post_kernel<<<blocks, THREADS>>>(in, out, ntiles);
}